// round 8
// baseline (speedup 1.0000x reference)
#include <cuda_runtime.h>

#define MAX_N 65536

__device__ float g_p[MAX_N];    // x . w_rel  per node
__device__ float g_r[MAX_N];    // x . w_root per node

// ---------------------------------------------------------------------------
// Kernel 1: per-node dual dot products (8 lanes/node, weights in smem).
// Also initializes out[g][o] = bproj[o] so k_pool can atomicAdd partials.
// ---------------------------------------------------------------------------
__global__ void k_scores(const float4* __restrict__ x4,
                         const float4* __restrict__ wrel4,
                         const float4* __restrict__ wroot4,
                         const float* __restrict__ bproj,
                         float* __restrict__ out,
                         int N, int d4, int outN, int odim) {
    extern __shared__ float4 wsm[];
    int t = threadIdx.x;
    for (int c = t; c < 2 * d4; c += blockDim.x)
        wsm[c] = (c < d4) ? wrel4[c] : wroot4[c - d4];
    __syncthreads();
    const float4* wa = wsm;
    const float4* wb = wsm + d4;

    int gt = blockIdx.x * blockDim.x + t;
    if (gt < outN) out[gt] = bproj[gt % odim];   // init output with bias

    int warp = gt >> 5;
    int lane = t & 31;
    int sub  = lane >> 3;
    int l8   = lane & 7;
    int node = warp * 4 + sub;
    if (node >= N) return;

    const float4* xr = x4 + (size_t)node * d4;
    float sp = 0.f, sr = 0.f;
#pragma unroll 8
    for (int c = l8; c < d4; c += 8) {
        float4 xv = xr[c];
        float4 a  = wa[c];
        float4 b  = wb[c];
        sp += xv.x * a.x + xv.y * a.y + xv.z * a.z + xv.w * a.w;
        sr += xv.x * b.x + xv.y * b.y + xv.z * b.z + xv.w * b.w;
    }
#pragma unroll
    for (int o = 4; o; o >>= 1) {
        sp += __shfl_xor_sync(0xffffffffu, sp, o);
        sr += __shfl_xor_sync(0xffffffffu, sr, o);
    }
    if (l8 == 0) {
        g_p[node] = sp;
        g_r[node] = sr;
    }
}

// ---------------------------------------------------------------------------
// Kernel 2: TWO CTAs per graph (grid 2B, 512 threads). Both CTAs duplicate
// the deterministic selection (edges + tanh + histogram top-k); each gathers
// only selected nodes with (i & 1) == half, projects its partial pooled
// (projection is linear), and atomicAdds into out (pre-set to bproj).
// ---------------------------------------------------------------------------
__global__ __launch_bounds__(512, 2)
void k_pool(const float* __restrict__ x,
            const int* __restrict__ ei,
            const float* __restrict__ brel,
            const float* __restrict__ wproj,
            float* __restrict__ out,
            int n, int k, int d, int odim, int E, int Eg, int nrep4) {
    extern __shared__ unsigned char sm[];
    float* p_s     = (float*)sm;                                 // n
    float* agg_s   = p_s + n;                                    // n
    unsigned* ubits = (unsigned*)(agg_s + n);                    // n
    float* svals   = (float*)(ubits + n);                        // k
    int*   sidx    = (int*)(svals + k);                          // k
    unsigned* hist = (unsigned*)(sidx + k);                      // 256
    unsigned* cgt  = hist + 256;                                 // 256
    uint2* list    = (uint2*)(cgt + 256);                        // n
    float* part    = (float*)(list + n);                         // nrep4 * d
    float* pooled  = part + nrep4 * d;                           // d
    int*   ctrl    = (int*)(pooled + d);                         // cnt, m, tb, krem

    const int g2   = blockIdx.x;
    const int g    = g2 >> 1;
    const int half = g2 & 1;
    const int t    = threadIdx.x;
    const int base = g * n;
    const int nt   = blockDim.x;

    if (t < 4) ctrl[t] = 0;
    for (int b = t; b < 256; b += nt) hist[b] = 0;
    for (int i = t; i < n; i += nt) {
        p_s[i]   = g_p[base + i];
        agg_s[i] = 0.f;
    }
    __syncthreads();

    // ---- edge aggregation (duplicated in both CTAs; deterministic sum set) ----
    {
        const int eb = g * Eg;
        for (int e = t; e < Eg; e += nt) {
            int s  = ei[eb + e] - base;
            int dd = ei[E + eb + e] - base;
            atomicAdd(&agg_s[dd], p_s[s]);
        }
    }
    __syncthreads();

    // ---- tanh score -> monotone bits + bucket histogram ----
    for (int i = t; i < n; i += nt) {
        float s = tanhf(agg_s[i] + brel[0] + g_r[base + i]);
        unsigned u = __float_as_uint(s);
        u = (u & 0x80000000u) ? ~u : (u | 0x80000000u);
        ubits[i] = u;
        atomicAdd(&hist[u >> 24], 1u);
    }
    __syncthreads();

    // ---- suffix counts + threshold bucket ----
    for (int b = t; b < 256; b += nt) {
        unsigned s = 0;
        for (int j = b + 1; j < 256; j++) s += hist[j];
        cgt[b] = s;
        if (s < (unsigned)k && (unsigned)k <= s + hist[b]) {
            ctrl[2] = b;
            ctrl[3] = k - (int)s;
        }
    }
    __syncthreads();

    const int tb   = ctrl[2];
    const int krem = ctrl[3];

    // ---- emit: clear winners filtered by parity; threshold bucket -> list ----
    for (int i = t; i < n; i += nt) {
        unsigned u = ubits[i];
        int b = (int)(u >> 24);
        if (b > tb) {
            if ((i & 1) == half) {
                int pos = atomicAdd(&ctrl[0], 1);
                unsigned fu = (u & 0x80000000u) ? (u & 0x7fffffffu) : ~u;
                svals[pos] = __uint_as_float(fu);
                sidx[pos]  = i;
            }
        } else if (b == tb) {
            int pos = atomicAdd(&ctrl[1], 1);
            list[pos] = make_uint2(u, (unsigned)i);
        }
    }
    __syncthreads();

    // ---- fine rank within threshold bucket (jax tie-break: smaller idx wins) ----
    {
        const int m = ctrl[1];
        for (int j = t; j < m; j += nt) {
            uint2 me = list[j];
            int r = 0;
            for (int l = 0; l < m; l++) {
                uint2 o = list[l];
                r += (o.x > me.x) || (o.x == me.x && o.y < me.y);
            }
            if (r < krem && ((int)me.y & 1) == half) {
                int pos = atomicAdd(&ctrl[0], 1);
                unsigned fu = (me.x & 0x80000000u) ? (me.x & 0x7fffffffu) : ~me.x;
                svals[pos] = __uint_as_float(fu);
                sidx[pos]  = (int)me.y;
            }
        }
    }
    __syncthreads();

    // ---- float4 gather over this CTA's subset ----
    const int cnt = ctrl[0];
    {
        const int d4   = d >> 2;
        const int col4 = t % d4;
        const int rep  = t / d4;
        const int per  = (cnt + nrep4 - 1) / nrep4;
        const int j0   = rep * per;
        const int j1   = min(j0 + per, cnt);
        const float4* x4 = (const float4*)x;
        float4 a0 = {0,0,0,0}, a1 = {0,0,0,0}, a2 = {0,0,0,0}, a3 = {0,0,0,0};
        int j = j0;
        for (; j + 4 <= j1; j += 4) {
            float v0 = svals[j], v1 = svals[j+1], v2 = svals[j+2], v3 = svals[j+3];
            int   r0 = sidx[j],  r1 = sidx[j+1],  r2 = sidx[j+2],  r3 = sidx[j+3];
            float4 q0 = x4[(size_t)(base + r0) * d4 + col4];
            float4 q1 = x4[(size_t)(base + r1) * d4 + col4];
            float4 q2 = x4[(size_t)(base + r2) * d4 + col4];
            float4 q3 = x4[(size_t)(base + r3) * d4 + col4];
            a0.x += v0*q0.x; a0.y += v0*q0.y; a0.z += v0*q0.z; a0.w += v0*q0.w;
            a1.x += v1*q1.x; a1.y += v1*q1.y; a1.z += v1*q1.z; a1.w += v1*q1.w;
            a2.x += v2*q2.x; a2.y += v2*q2.y; a2.z += v2*q2.z; a2.w += v2*q2.w;
            a3.x += v3*q3.x; a3.y += v3*q3.y; a3.z += v3*q3.z; a3.w += v3*q3.w;
        }
        for (; j < j1; j++) {
            float v = svals[j];
            float4 q = x4[(size_t)(base + sidx[j]) * d4 + col4];
            a0.x += v*q.x; a0.y += v*q.y; a0.z += v*q.z; a0.w += v*q.w;
        }
        float4 s;
        s.x = a0.x + a1.x + a2.x + a3.x;
        s.y = a0.y + a1.y + a2.y + a3.y;
        s.z = a0.z + a1.z + a2.z + a3.z;
        s.w = a0.w + a1.w + a2.w + a3.w;
        ((float4*)part)[rep * d4 + col4] = s;
    }
    __syncthreads();

    // partial pooled (this CTA's subset, scaled by full 1/k)
    for (int i = t; i < d; i += nt) {
        float s = 0.f;
        for (int rr = 0; rr < nrep4; rr++) s += part[rr * d + i];
        pooled[i] = s / (float)k;
    }
    __syncthreads();

    // ---- project partial pooled (linear => partials commute); atomicAdd out --
    {
        const int o    = t % odim;
        const int p    = t / odim;
        const int nrep = nt / odim;
        const int per  = (d + nrep - 1) / nrep;
        const int d0   = p * per;
        const int d1   = min(d0 + per, d);
        float a0 = 0.f, a1 = 0.f, a2 = 0.f, a3 = 0.f;
        int dd = d0;
        for (; dd + 4 <= d1; dd += 4) {
            a0 += pooled[dd + 0] * wproj[(size_t)(dd + 0) * odim + o];
            a1 += pooled[dd + 1] * wproj[(size_t)(dd + 1) * odim + o];
            a2 += pooled[dd + 2] * wproj[(size_t)(dd + 2) * odim + o];
            a3 += pooled[dd + 3] * wproj[(size_t)(dd + 3) * odim + o];
        }
        for (; dd < d1; dd++)
            a0 += pooled[dd] * wproj[(size_t)dd * odim + o];
        part[p * odim + o] = a0 + a1 + a2 + a3;
    }
    __syncthreads();

    if (t < odim) {
        const int nrep = nt / odim;
        float s = 0.f;
        for (int rr = 0; rr < nrep; rr++) s += part[rr * odim + t];
        atomicAdd(&out[(size_t)g * odim + t], s);
    }
}

// ---------------------------------------------------------------------------
extern "C" void kernel_launch(void* const* d_in, const int* in_sizes, int n_in,
                              void* d_out, int out_size) {
    const float* x     = (const float*)d_in[0];
    const int*   ei    = (const int*)d_in[1];
    const float* wrel  = (const float*)d_in[4];
    const float* brel  = (const float*)d_in[5];
    const float* wroot = (const float*)d_in[6];
    const float* wproj = (const float*)d_in[7];
    const float* bproj = (const float*)d_in[8];
    float* out = (float*)d_out;

    const int odim = in_sizes[8];
    const int d    = in_sizes[7] / odim;
    const int N    = in_sizes[0] / d;
    const int E    = in_sizes[1] / 2;
    const int B    = out_size / odim;
    const int n    = N / B;
    const int k    = (n + 1) / 2;     // ceil(0.5 * n), RATIO = 0.5
    const int Eg   = E / B;
    const int d4   = d / 4;
    const int nrep4 = 512 / d4;       // gather replicas (8 for d=256)

    // K1: scores + output init
    int warps = (N + 3) / 4;
    size_t smem1 = (size_t)(2 * d4) * sizeof(float4);
    k_scores<<<(warps * 32 + 255) / 256, 256, smem1>>>(
        (const float4*)x, (const float4*)wrel, (const float4*)wroot,
        bproj, out, N, d4, B * odim, odim);

    // K2: 2 CTAs per graph
    const int pd = d > odim ? d : odim;
    size_t smem2 = (size_t)n * 8                 // p, agg
                 + (size_t)n * 4                 // ubits
                 + (size_t)k * 8                 // svals + sidx
                 + 512 * 4                       // hist + cgt
                 + (size_t)n * 8                 // list
                 + (size_t)nrep4 * pd * 4        // part
                 + (size_t)d * 4                 // pooled
                 + 32;                           // ctrl + pad
    k_pool<<<2 * B, 512, smem2>>>(x, ei, brel, wproj, out,
                                  n, k, d, odim, E, Eg, nrep4);
}